// round 8
// baseline (speedup 1.0000x reference)
#include <cuda_runtime.h>
#include <cuda_bf16.h>
#include <cstdint>

// ---------------------------------------------------------------------------
// FeatureAttentionPerFeature — mma.sync bf16 3-term split + cp.async pipeline
//   scores[b,f] = feat_f[b] . (Wk_f^T q)/sqrt(128)
//   w = softmax_f(scores)
//   combined = (w-scaled concat feats) @ Wv_all^T
// Output: [ combined (B*128) | attn_weights (B*8) ]
// R8: cp.async double-buffered raw A + triple-buffered B, 1 CTA/SM
// ---------------------------------------------------------------------------

#define NF     8
#define HID    128
#define KTOT   1664
#define BATCHN 32768
#define MBLK   128
#define KCH    64
#define NCH    (KTOT/KCH)    // 26
#define NTHR   256
#define RSTRIDE 144          // bf16 tile row stride BYTES, conflict-free

__device__ constexpr int DIMS_C[NF]   = {32, 64, 96, 128, 192, 256, 384, 512};
__device__ constexpr int OFFS_C[NF+1] = {0, 32, 96, 192, 320, 512, 768, 1152, 1664};
__constant__ int gDIMS[NF]   = {32, 64, 96, 128, 192, 256, 384, 512};
__constant__ int gOFFS[NF+1] = {0, 32, 96, 192, 320, 512, 768, 1152, 1664};

__device__ float g_c[KTOT];
__device__ __nv_bfloat16 g_Bh[HID * KTOT];   // Wv hi, [n][k]
__device__ __nv_bfloat16 g_Bl[HID * KTOT];   // Wv lo residual

struct Ptrs {
    const float* feat[NF];
    const float* Wk[NF];
    const float* Wv[NF];
    const float* q;
};

// ---------------- helpers ----------------
__device__ __forceinline__ uint32_t smem_u32(const void* p) {
    uint32_t a;
    asm("{ .reg .u64 t; cvta.to.shared.u64 t, %1; cvt.u32.u64 %0, t; }" : "=r"(a) : "l"(p));
    return a;
}
__device__ __forceinline__ void ldsm_x4(uint32_t* r, uint32_t a) {
    asm volatile("ldmatrix.sync.aligned.m8n8.x4.shared.b16 {%0,%1,%2,%3}, [%4];"
                 : "=r"(r[0]), "=r"(r[1]), "=r"(r[2]), "=r"(r[3]) : "r"(a));
}
__device__ __forceinline__ void mma_bf16(float* c, const uint32_t* a, const uint32_t* b) {
    asm volatile(
        "mma.sync.aligned.m16n8k16.row.col.f32.bf16.bf16.f32 "
        "{%0,%1,%2,%3}, {%4,%5,%6,%7}, {%8,%9}, {%0,%1,%2,%3};"
        : "+f"(c[0]), "+f"(c[1]), "+f"(c[2]), "+f"(c[3])
        : "r"(a[0]), "r"(a[1]), "r"(a[2]), "r"(a[3]), "r"(b[0]), "r"(b[1]));
}
__device__ __forceinline__ void cpa16(uint32_t dst, const void* src) {
    asm volatile("cp.async.cg.shared.global [%0], [%1], 16;" :: "r"(dst), "l"(src));
}
__device__ __forceinline__ void cpa_commit() {
    asm volatile("cp.async.commit_group;" ::: "memory");
}
__device__ __forceinline__ void cpa_wait1() {
    asm volatile("cp.async.wait_group 1;" ::: "memory");
}
__device__ __forceinline__ int ffind(int k) {
    int f = 7;
    if (k < 1152) f = 6;
    if (k < 768)  f = 5;
    if (k < 512)  f = 4;
    if (k < 320)  f = 3;
    if (k < 192)  f = 2;
    if (k < 96)   f = 1;
    if (k < 32)   f = 0;
    return f;
}

// ---------------- SMEM layout (dynamic, bytes) ----------------
#define OFF_WS   0                     // 128*8*4 = 4096
#define OFF_AH   4096                  // 18432
#define OFF_AL   22528                 // 18432
#define OFF_BT   40960                 // 3 bufs x (Bh 18432 + Bl 18432)
#define BSTRIDE  36864
#define OFF_RAW  151552                // 2 bufs x 32768 raw fp32 A
#define SMEM_TOT 217088
#define OFF_CS   OFF_AH                // phase-1 c staging (overwritten later)

// ---------------------------------------------------------------------------
__global__ void prep_kernel(Ptrs p) {
    int tid = blockIdx.x * blockDim.x + threadIdx.x;

    if (tid < KTOT * 32) {
        int k = tid >> 5, ln = tid & 31;
        int f = ffind(k);
        int j = k - gOFFS[f];
        int d = gDIMS[f];
        const float* W = p.Wk[f];
        float s = 0.f;
        #pragma unroll
        for (int h = ln; h < HID; h += 32) s += W[h * d + j] * p.q[h];
        #pragma unroll
        for (int o = 16; o; o >>= 1) s += __shfl_xor_sync(0xffffffffu, s, o);
        if (ln == 0) g_c[k] = s * 0.08838834764831845f;
    }

    if (tid < HID * KTOT) {
        int n = tid / KTOT;
        int k = tid % KTOT;
        int f = ffind(k);
        int j = k - gOFFS[f];
        float val = p.Wv[f][n * gDIMS[f] + j];
        __nv_bfloat16 hi = __float2bfloat16_rn(val);
        __nv_bfloat16 lo = __float2bfloat16_rn(val - __bfloat162float(hi));
        g_Bh[tid] = hi;
        g_Bl[tid] = lo;
    }
}

// ---------------------------------------------------------------------------
// issue cp.async group for one chunk: raw A (8x16B/thr) + B tiles (8x16B/thr)
// ---------------------------------------------------------------------------
__device__ __forceinline__ void issue_chunk(const Ptrs& p, uint32_t sb,
                                            int row0, int ch, int t) {
    const int k0   = ch * KCH;
    const int bufA = ch & 1;
    const int bufB = ch % 3;
    const uint32_t rawb = sb + OFF_RAW + bufA * 32768;
    // A raw: 128 rows x 256B
    #pragma unroll
    for (int it = 0; it < 8; it++) {
        int g   = it * 256 + t;        // 0..2047
        int row = g >> 4;
        int c16 = g & 15;
        int kg  = k0 + c16 * 4;
        int f   = ffind(kg);
        int j   = kg - gOFFS[f];
        const float* src = p.feat[f] + (size_t)(row0 + row) * gDIMS[f] + j;
        cpa16(rawb + row * 256 + c16 * 16, src);
    }
    // B tiles: direct into swizzle-free RSTRIDE layout
    const uint32_t bh = sb + OFF_BT + bufB * BSTRIDE;
    #pragma unroll
    for (int it = 0; it < 4; it++) {
        int g  = it * 256 + t;         // 0..1023
        int n  = g >> 3;
        int kq = g & 7;
        size_t goff = (size_t)n * KTOT + k0 + kq * 8;
        uint32_t off = (uint32_t)(n * RSTRIDE + kq * 16);
        cpa16(bh + off, &g_Bh[goff]);
        cpa16(bh + 18432 + off, &g_Bl[goff]);
    }
}

// ---------------------------------------------------------------------------
// main kernel: grid 256 x 256 threads, 1 CTA/SM (212KB smem)
// ---------------------------------------------------------------------------
__global__ void __launch_bounds__(NTHR, 1)
main_kernel(Ptrs p, float* __restrict__ out) {
    extern __shared__ char smem[];
    const uint32_t sb = smem_u32(smem);
    const int t    = threadIdx.x;
    const int lane = t & 31;
    const int wid  = t >> 5;
    const int wm   = wid >> 2;
    const int wn   = wid & 3;
    const int row0 = blockIdx.x * MBLK;

    float* ws_s = (float*)(smem + OFF_WS);
    float* cs   = (float*)(smem + OFF_CS);

    // prologue: start DMA for chunks 0,1 before phase 1
    issue_chunk(p, sb, row0, 0, t); cpa_commit();
    issue_chunk(p, sb, row0, 1, t); cpa_commit();

    // stage c into (future Ah) smem
    for (int i = t; i < KTOT; i += NTHR) cs[i] = g_c[i];
    __syncthreads();

    // ---- phase 1: warp-per-row coalesced scores + softmax ----
    {
        #pragma unroll 1
        for (int rr = 0; rr < 16; rr++) {
            const int lrow = wid * 16 + rr;
            const int row  = row0 + lrow;
            float sc[NF];
            #pragma unroll
            for (int f = 0; f < NF; f++) {
                const int d = DIMS_C[f];
                float s = 0.f;
                #pragma unroll
                for (int j0 = 0; j0 < d; j0 += 128) {
                    int j = j0 + lane * 4;
                    if (j < d) {
                        float4 a = *(const float4*)(p.feat[f] + (size_t)row * d + j);
                        float4 b = *(const float4*)(cs + OFFS_C[f] + j);
                        s += a.x * b.x + a.y * b.y + a.z * b.z + a.w * b.w;
                    }
                }
                #pragma unroll
                for (int o = 16; o; o >>= 1) s += __shfl_xor_sync(0xffffffffu, s, o);
                sc[f] = s;
            }
            float m = sc[0];
            #pragma unroll
            for (int f = 1; f < NF; f++) m = fmaxf(m, sc[f]);
            float sum = 0.f;
            #pragma unroll
            for (int f = 0; f < NF; f++) { sc[f] = expf(sc[f] - m); sum += sc[f]; }
            const float inv = 1.f / sum;
            if (lane == 0) {
                float4 w0 = make_float4(sc[0] * inv, sc[1] * inv, sc[2] * inv, sc[3] * inv);
                float4 w1 = make_float4(sc[4] * inv, sc[5] * inv, sc[6] * inv, sc[7] * inv);
                *(float4*)(ws_s + lrow * NF)     = w0;
                *(float4*)(ws_s + lrow * NF + 4) = w1;
                float* ao = out + (size_t)BATCHN * HID + (size_t)row * NF;
                *(float4*)(ao)     = w0;
                *(float4*)(ao + 4) = w1;
            }
        }
    }

    // ---- mainloop ----
    float acc[4][4][4];
    #pragma unroll
    for (int mf = 0; mf < 4; mf++)
        #pragma unroll
        for (int nf = 0; nf < 4; nf++)
            #pragma unroll
            for (int r = 0; r < 4; r++) acc[mf][nf][r] = 0.f;

    const uint32_t aoff = (uint32_t)((wm * 64 + (lane & 15)) * RSTRIDE + ((lane >> 4) * 8) * 2);
    const uint32_t boff = (uint32_t)((wn * 32 + ((lane >> 4) * 8) + (lane & 7)) * RSTRIDE +
                                     (((lane >> 3) & 1) * 8) * 2);
    const uint32_t sAh = sb + OFF_AH, sAl = sb + OFF_AL;

    for (int ch = 0; ch < NCH; ch++) {
        const int k0   = ch * KCH;
        const int bufA = ch & 1;
        const int bufB = ch % 3;

        cpa_wait1();          // chunk ch landed (ch+1 may be in flight)
        __syncthreads();      // + previous MMA done reading Ah/Al, phase-1 ws visible

        // --- convert raw fp32 (smem) -> weighted hi/lo bf16 tiles ---
        {
            const uint32_t rawb = sb + OFF_RAW + bufA * 32768;
            #pragma unroll
            for (int it = 0; it < 4; it++) {
                int g   = it * 256 + t;    // 0..1023
                int row = g >> 3;
                int kq  = g & 7;
                int f   = ffind(k0 + kq * 8);
                float4 v0 = *(const float4*)(smem + (rawb - sb) + row * 256 + kq * 32);
                float4 v1 = *(const float4*)(smem + (rawb - sb) + row * 256 + kq * 32 + 16);
                float w = ws_s[row * NF + f];
                float x[8] = {v0.x * w, v0.y * w, v0.z * w, v0.w * w,
                              v1.x * w, v1.y * w, v1.z * w, v1.w * w};
                uint32_t h[4], l[4];
                #pragma unroll
                for (int q = 0; q < 4; q++) {
                    float a0 = x[2 * q], a1 = x[2 * q + 1];
                    __nv_bfloat16 b0 = __float2bfloat16_rn(a0);
                    __nv_bfloat16 b1 = __float2bfloat16_rn(a1);
                    __nv_bfloat16 c0 = __float2bfloat16_rn(a0 - __bfloat162float(b0));
                    __nv_bfloat16 c1 = __float2bfloat16_rn(a1 - __bfloat162float(b1));
                    h[q] = (uint32_t)__bfloat16_as_ushort(b0) | ((uint32_t)__bfloat16_as_ushort(b1) << 16);
                    l[q] = (uint32_t)__bfloat16_as_ushort(c0) | ((uint32_t)__bfloat16_as_ushort(c1) << 16);
                }
                uint32_t off = (uint32_t)(row * RSTRIDE + kq * 16);
                *(uint4*)(smem + OFF_AH + off) = make_uint4(h[0], h[1], h[2], h[3]);
                *(uint4*)(smem + OFF_AL + off) = make_uint4(l[0], l[1], l[2], l[3]);
            }
        }
        __syncthreads();      // convert done; raw buf free; tiles visible

        // prefetch chunk ch+2 (raw A buf now free, B buf (ch+2)%3 unused)
        if (ch + 2 < NCH) issue_chunk(p, sb, row0, ch + 2, t);
        cpa_commit();         // always commit to keep group accounting uniform

        // --- tensor-core phase ---
        const uint32_t sBh = sb + OFF_BT + bufB * BSTRIDE;
        const uint32_t sBl = sBh + 18432;
        #pragma unroll
        for (int ks = 0; ks < 4; ks++) {
            const uint32_t koff = ks * 32;
            uint32_t a[4][4];
            #pragma unroll
            for (int mf = 0; mf < 4; mf++)
                ldsm_x4(a[mf], sAh + aoff + mf * (16 * RSTRIDE) + koff);

            uint32_t bh[4][2], bl[4][2];
            #pragma unroll
            for (int bq = 0; bq < 2; bq++) {
                uint32_t r[4];
                ldsm_x4(r, sBh + boff + bq * (16 * RSTRIDE) + koff);
                bh[bq * 2][0] = r[0]; bh[bq * 2][1] = r[1];
                bh[bq * 2 + 1][0] = r[2]; bh[bq * 2 + 1][1] = r[3];
                ldsm_x4(r, sBl + boff + bq * (16 * RSTRIDE) + koff);
                bl[bq * 2][0] = r[0]; bl[bq * 2][1] = r[1];
                bl[bq * 2 + 1][0] = r[2]; bl[bq * 2 + 1][1] = r[3];
            }
            #pragma unroll
            for (int mf = 0; mf < 4; mf++)
                #pragma unroll
                for (int nf = 0; nf < 4; nf++) mma_bf16(acc[mf][nf], a[mf], bh[nf]);
            #pragma unroll
            for (int mf = 0; mf < 4; mf++)
                #pragma unroll
                for (int nf = 0; nf < 4; nf++) mma_bf16(acc[mf][nf], a[mf], bl[nf]);
            #pragma unroll
            for (int mf = 0; mf < 4; mf++)
                ldsm_x4(a[mf], sAl + aoff + mf * (16 * RSTRIDE) + koff);
            #pragma unroll
            for (int mf = 0; mf < 4; mf++)
                #pragma unroll
                for (int nf = 0; nf < 4; nf++) mma_bf16(acc[mf][nf], a[mf], bh[nf]);
        }
    }

    // ---- epilogue ----
    #pragma unroll
    for (int mf = 0; mf < 4; mf++) {
        #pragma unroll
        for (int nf = 0; nf < 4; nf++) {
            int r0 = row0 + wm * 64 + mf * 16 + (lane >> 2);
            int c  = wn * 32 + nf * 8 + (lane & 3) * 2;
            *(float2*)(out + (size_t)r0 * HID + c) =
                make_float2(acc[mf][nf][0], acc[mf][nf][1]);
            *(float2*)(out + (size_t)(r0 + 8) * HID + c) =
                make_float2(acc[mf][nf][2], acc[mf][nf][3]);
        }
    }
}

// ---------------------------------------------------------------------------
extern "C" void kernel_launch(void* const* d_in, const int* in_sizes, int n_in,
                              void* d_out, int out_size) {
    static const int dims[NF] = {32, 64, 96, 128, 192, 256, 384, 512};
    Ptrs p;
    int wseen[NF] = {0};

    for (int i = 0; i < n_in; i++) {
        const float* ptr = (const float*)d_in[i];
        int s = in_sizes[i];
        if (s == HID) { p.q = ptr; continue; }
        bool matched = false;
        for (int f = 0; f < NF; f++)
            if (s == BATCHN * dims[f]) { p.feat[f] = ptr; matched = true; break; }
        if (matched) continue;
        for (int f = 0; f < NF; f++)
            if (s == HID * dims[f]) {
                if (!wseen[f]) { p.Wk[f] = ptr; wseen[f] = 1; }
                else           { p.Wv[f] = ptr; }
                break;
            }
    }

    cudaFuncSetAttribute(main_kernel, cudaFuncAttributeMaxDynamicSharedMemorySize, SMEM_TOT);

    prep_kernel<<<(HID * KTOT + 255) / 256, 256>>>(p);
    main_kernel<<<BATCHN / MBLK, NTHR, SMEM_TOT>>>(p, (float*)d_out);
}

// round 9
// speedup vs baseline: 1.1351x; 1.1351x over previous
#include <cuda_runtime.h>
#include <cuda_bf16.h>
#include <cstdint>

// ---------------------------------------------------------------------------
// FeatureAttentionPerFeature — mma.sync bf16 3-term split, cp.async pipeline
// R9: KCH=32, double-buffered raw-A + B via cp.async, 2 CTAs/SM preserved.
//   scores[b,f] = feat_f[b] . (Wk_f^T q)/sqrt(128)
//   w = softmax_f(scores); combined = (w-scaled concat feats) @ Wv_all^T
// Output: [ combined (B*128) | attn_weights (B*8) ]
// ---------------------------------------------------------------------------

#define NF     8
#define HID    128
#define KTOT   1664
#define BATCHN 32768
#define MBLK   128
#define KCH    32
#define NCH    (KTOT/KCH)    // 52
#define NTHR   256
#define TSTR   80            // bf16 tile row stride (bytes): conflict-free
#define RAWSTR 144           // raw fp32 row stride (bytes): conflict-free

__device__ constexpr int DIMS_C[NF]   = {32, 64, 96, 128, 192, 256, 384, 512};
__device__ constexpr int OFFS_C[NF+1] = {0, 32, 96, 192, 320, 512, 768, 1152, 1664};
__constant__ int gDIMS[NF]   = {32, 64, 96, 128, 192, 256, 384, 512};
__constant__ int gOFFS[NF+1] = {0, 32, 96, 192, 320, 512, 768, 1152, 1664};

__device__ float g_c[KTOT];
__device__ __nv_bfloat16 g_Bh[HID * KTOT];   // Wv hi, [n][k]
__device__ __nv_bfloat16 g_Bl[HID * KTOT];   // Wv lo residual

struct Ptrs {
    const float* feat[NF];
    const float* Wk[NF];
    const float* Wv[NF];
    const float* q;
};

// ---------------- helpers ----------------
__device__ __forceinline__ uint32_t smem_u32(const void* p) {
    uint32_t a;
    asm("{ .reg .u64 t; cvta.to.shared.u64 t, %1; cvt.u32.u64 %0, t; }" : "=r"(a) : "l"(p));
    return a;
}
__device__ __forceinline__ void ldsm_x4(uint32_t* r, uint32_t a) {
    asm volatile("ldmatrix.sync.aligned.m8n8.x4.shared.b16 {%0,%1,%2,%3}, [%4];"
                 : "=r"(r[0]), "=r"(r[1]), "=r"(r[2]), "=r"(r[3]) : "r"(a));
}
__device__ __forceinline__ void mma_bf16(float* c, const uint32_t* a, const uint32_t* b) {
    asm volatile(
        "mma.sync.aligned.m16n8k16.row.col.f32.bf16.bf16.f32 "
        "{%0,%1,%2,%3}, {%4,%5,%6,%7}, {%8,%9}, {%0,%1,%2,%3};"
        : "+f"(c[0]), "+f"(c[1]), "+f"(c[2]), "+f"(c[3])
        : "r"(a[0]), "r"(a[1]), "r"(a[2]), "r"(a[3]), "r"(b[0]), "r"(b[1]));
}
__device__ __forceinline__ void cpa16(uint32_t dst, const void* src) {
    asm volatile("cp.async.cg.shared.global [%0], [%1], 16;" :: "r"(dst), "l"(src));
}
__device__ __forceinline__ void cpa_commit() {
    asm volatile("cp.async.commit_group;" ::: "memory");
}
__device__ __forceinline__ void cpa_wait1() {
    asm volatile("cp.async.wait_group 1;" ::: "memory");
}
__device__ __forceinline__ int ffind(int k) {
    int f = 7;
    if (k < 1152) f = 6;
    if (k < 768)  f = 5;
    if (k < 512)  f = 4;
    if (k < 320)  f = 3;
    if (k < 192)  f = 2;
    if (k < 96)   f = 1;
    if (k < 32)   f = 0;
    return f;
}

// ---------------- SMEM layout (dynamic, bytes) ----------------
#define OFF_WS   0                      // ws [f][row] 8*128*4 = 4096
#define OFF_CS   4096                   // 1664*4 = 6656
#define OFF_AH   10752                  // 128*80 = 10240
#define OFF_AL   20992                  // 10240
#define OFF_B    31232                  // 2 bufs x (Bh 10240 + Bl 10240) = 40960
#define OFF_RAW  72192                  // 2 bufs x 128*144 = 36864
#define SMEM_TOT 109056

// ---------------------------------------------------------------------------
__global__ void prep_kernel(Ptrs p) {
    int tid = blockIdx.x * blockDim.x + threadIdx.x;

    if (tid < KTOT * 32) {
        int k = tid >> 5, ln = tid & 31;
        int f = ffind(k);
        int j = k - gOFFS[f];
        int d = gDIMS[f];
        const float* W = p.Wk[f];
        float s = 0.f;
        #pragma unroll
        for (int h = ln; h < HID; h += 32) s += W[h * d + j] * p.q[h];
        #pragma unroll
        for (int o = 16; o; o >>= 1) s += __shfl_xor_sync(0xffffffffu, s, o);
        if (ln == 0) g_c[k] = s * 0.08838834764831845f;
    }

    if (tid < HID * KTOT) {
        int n = tid / KTOT;
        int k = tid % KTOT;
        int f = ffind(k);
        int j = k - gOFFS[f];
        float val = p.Wv[f][n * gDIMS[f] + j];
        __nv_bfloat16 hi = __float2bfloat16_rn(val);
        __nv_bfloat16 lo = __float2bfloat16_rn(val - __bfloat162float(hi));
        g_Bh[tid] = hi;
        g_Bl[tid] = lo;
    }
}

// ---------------------------------------------------------------------------
// cp.async issue helpers (all 256 threads participate)
// ---------------------------------------------------------------------------
__device__ __forceinline__ void issue_rawA(const Ptrs& p, uint32_t sb,
                                           int row0, int ch, int t) {
    const int k0  = ch * KCH;
    const int f   = ffind(k0);
    const int d   = gDIMS[f];
    const int j0  = k0 - gOFFS[f];
    const uint32_t dst0 = sb + OFF_RAW + (ch & 1) * 18432;
    #pragma unroll
    for (int it = 0; it < 4; it++) {
        int g   = it * 256 + t;     // 0..1023
        int row = g >> 3;
        int c16 = g & 7;            // 8 x 16B = 128B per row
        const float* src = p.feat[f] + (size_t)(row0 + row) * d + j0 + c16 * 4;
        cpa16(dst0 + row * RAWSTR + c16 * 16, src);
    }
}
__device__ __forceinline__ void issue_B(uint32_t sb, int ch, int t) {
    const int k0 = ch * KCH;
    const uint32_t dh = sb + OFF_B + (ch & 1) * 20480;
    #pragma unroll
    for (int it = 0; it < 2; it++) {
        int g  = it * 256 + t;      // 0..511
        int n  = g >> 2;
        int kq = g & 3;             // 4 x 16B = 64B per row
        size_t goff = (size_t)n * KTOT + k0 + kq * 8;
        uint32_t off = (uint32_t)(n * TSTR + kq * 16);
        cpa16(dh + off, &g_Bh[goff]);
        cpa16(dh + 10240 + off, &g_Bl[goff]);
    }
}

// ---------------------------------------------------------------------------
// main kernel: grid 256 x 256 threads, 2 CTAs/SM
// ---------------------------------------------------------------------------
__global__ void __launch_bounds__(NTHR, 2)
main_kernel(Ptrs p, float* __restrict__ out) {
    extern __shared__ char smem[];
    const uint32_t sb = smem_u32(smem);
    const int t    = threadIdx.x;
    const int lane = t & 31;
    const int wid  = t >> 5;
    const int wm   = wid >> 2;
    const int wn   = wid & 3;
    const int row0 = blockIdx.x * MBLK;

    float* ws_s = (float*)(smem + OFF_WS);   // [f][row]
    float* cs   = (float*)(smem + OFF_CS);

    for (int i = t; i < KTOT; i += NTHR) cs[i] = g_c[i];
    __syncthreads();

    // ---- phase 1: warp-per-row coalesced scores + softmax ----
    {
        #pragma unroll 1
        for (int rr = 0; rr < 16; rr++) {
            const int lrow = wid * 16 + rr;
            const int row  = row0 + lrow;
            float sc[NF];
            #pragma unroll
            for (int f = 0; f < NF; f++) {
                const int d = DIMS_C[f];
                float s = 0.f;
                #pragma unroll
                for (int j0 = 0; j0 < d; j0 += 128) {
                    int j = j0 + lane * 4;
                    if (j < d) {
                        float4 a = *(const float4*)(p.feat[f] + (size_t)row * d + j);
                        float4 b = *(const float4*)(cs + OFFS_C[f] + j);
                        s += a.x * b.x + a.y * b.y + a.z * b.z + a.w * b.w;
                    }
                }
                #pragma unroll
                for (int o = 16; o; o >>= 1) s += __shfl_xor_sync(0xffffffffu, s, o);
                sc[f] = s;
            }
            float m = sc[0];
            #pragma unroll
            for (int f = 1; f < NF; f++) m = fmaxf(m, sc[f]);
            float sum = 0.f;
            #pragma unroll
            for (int f = 0; f < NF; f++) { sc[f] = expf(sc[f] - m); sum += sc[f]; }
            const float inv = 1.f / sum;
            if (lane == 0) {
                #pragma unroll
                for (int f = 0; f < NF; f++) ws_s[f * 128 + lrow] = sc[f] * inv;
                float* ao = out + (size_t)BATCHN * HID + (size_t)row * NF;
                *(float4*)(ao)     = make_float4(sc[0] * inv, sc[1] * inv, sc[2] * inv, sc[3] * inv);
                *(float4*)(ao + 4) = make_float4(sc[4] * inv, sc[5] * inv, sc[6] * inv, sc[7] * inv);
            }
        }
    }

    // ---- prologue: chunks 0,1 in flight ----
    issue_rawA(p, sb, row0, 0, t); issue_B(sb, 0, t); cpa_commit();
    issue_rawA(p, sb, row0, 1, t); issue_B(sb, 1, t); cpa_commit();

    // ---- mainloop ----
    float acc[4][4][4];
    #pragma unroll
    for (int mf = 0; mf < 4; mf++)
        #pragma unroll
        for (int nf = 0; nf < 4; nf++)
            #pragma unroll
            for (int r = 0; r < 4; r++) acc[mf][nf][r] = 0.f;

    const uint32_t aoff = (uint32_t)((wm * 64 + (lane & 15)) * TSTR + (lane >> 4) * 16);
    const uint32_t boff = (uint32_t)((wn * 32 + (lane >> 4) * 8 + (lane & 7)) * TSTR +
                                     ((lane >> 3) & 1) * 16);
    const uint32_t sAh = sb + OFF_AH, sAl = sb + OFF_AL;

    for (int ch = 0; ch < NCH; ch++) {
        const int buf = ch & 1;

        cpa_wait1();         // chunk ch (rawA + B) landed
        __syncthreads();     // prev MMA done; ws visible (first iter)

        // issue B(ch+1): its buffer was consumed by chunk ch-1 (done at barrier)
        if (ch >= 1 && ch + 1 < NCH) issue_B(sb, ch + 1, t);
        cpa_commit();        // C_b

        // --- convert raw fp32 (smem) -> weighted hi/lo bf16 tiles ---
        {
            const int f = ffind(ch * KCH);
            const uint32_t rawb = OFF_RAW + buf * 18432;
            #pragma unroll
            for (int it = 0; it < 2; it++) {
                int row = t & 127;
                int kq  = (t >> 7) + 2 * it;      // 0..3 (8 k each)
                const char* rp = smem + rawb + row * RAWSTR + kq * 32;
                float4 v0 = *(const float4*)(rp);
                float4 v1 = *(const float4*)(rp + 16);
                float w = ws_s[f * 128 + row];
                float x[8] = {v0.x * w, v0.y * w, v0.z * w, v0.w * w,
                              v1.x * w, v1.y * w, v1.z * w, v1.w * w};
                uint32_t h[4], l[4];
                #pragma unroll
                for (int q = 0; q < 4; q++) {
                    float a0 = x[2 * q], a1 = x[2 * q + 1];
                    __nv_bfloat16 b0 = __float2bfloat16_rn(a0);
                    __nv_bfloat16 b1 = __float2bfloat16_rn(a1);
                    __nv_bfloat16 c0 = __float2bfloat16_rn(a0 - __bfloat162float(b0));
                    __nv_bfloat16 c1 = __float2bfloat16_rn(a1 - __bfloat162float(b1));
                    h[q] = (uint32_t)__bfloat16_as_ushort(b0) | ((uint32_t)__bfloat16_as_ushort(b1) << 16);
                    l[q] = (uint32_t)__bfloat16_as_ushort(c0) | ((uint32_t)__bfloat16_as_ushort(c1) << 16);
                }
                uint32_t off = (uint32_t)(row * TSTR + kq * 16);
                *(uint4*)(smem + OFF_AH + off) = make_uint4(h[0], h[1], h[2], h[3]);
                *(uint4*)(smem + OFF_AL + off) = make_uint4(l[0], l[1], l[2], l[3]);
            }
        }
        __syncthreads();     // tiles visible; raw buf free

        // issue rawA(ch+2): raw buf just freed by convert
        if (ch + 2 < NCH) issue_rawA(p, sb, row0, ch + 2, t);
        cpa_commit();        // C_a

        // --- tensor-core phase: 2 k16 steps ---
        const uint32_t sBh = sb + OFF_B + buf * 20480;
        const uint32_t sBl = sBh + 10240;
        #pragma unroll
        for (int ks = 0; ks < 2; ks++) {
            const uint32_t koff = ks * 32;
            uint32_t a[4][4];
            #pragma unroll
            for (int mf = 0; mf < 4; mf++)
                ldsm_x4(a[mf], sAh + aoff + mf * (16 * TSTR) + koff);

            uint32_t bh[4][2], bl[4][2];
            #pragma unroll
            for (int bq = 0; bq < 2; bq++) {
                uint32_t r[4];
                ldsm_x4(r, sBh + boff + bq * (16 * TSTR) + koff);
                bh[bq * 2][0] = r[0]; bh[bq * 2][1] = r[1];
                bh[bq * 2 + 1][0] = r[2]; bh[bq * 2 + 1][1] = r[3];
                ldsm_x4(r, sBl + boff + bq * (16 * TSTR) + koff);
                bl[bq * 2][0] = r[0]; bl[bq * 2][1] = r[1];
                bl[bq * 2 + 1][0] = r[2]; bl[bq * 2 + 1][1] = r[3];
            }
            #pragma unroll
            for (int mf = 0; mf < 4; mf++)
                #pragma unroll
                for (int nf = 0; nf < 4; nf++) mma_bf16(acc[mf][nf], a[mf], bh[nf]);
            #pragma unroll
            for (int mf = 0; mf < 4; mf++)
                #pragma unroll
                for (int nf = 0; nf < 4; nf++) mma_bf16(acc[mf][nf], a[mf], bl[nf]);
            #pragma unroll
            for (int mf = 0; mf < 4; mf++)
                ldsm_x4(a[mf], sAl + aoff + mf * (16 * TSTR) + koff);
            #pragma unroll
            for (int mf = 0; mf < 4; mf++)
                #pragma unroll
                for (int nf = 0; nf < 4; nf++) mma_bf16(acc[mf][nf], a[mf], bh[nf]);
        }
    }

    // ---- epilogue ----
    #pragma unroll
    for (int mf = 0; mf < 4; mf++) {
        #pragma unroll
        for (int nf = 0; nf < 4; nf++) {
            int r0 = row0 + wm * 64 + mf * 16 + (lane >> 2);
            int c  = wn * 32 + nf * 8 + (lane & 3) * 2;
            *(float2*)(out + (size_t)r0 * HID + c) =
                make_float2(acc[mf][nf][0], acc[mf][nf][1]);
            *(float2*)(out + (size_t)(r0 + 8) * HID + c) =
                make_float2(acc[mf][nf][2], acc[mf][nf][3]);
        }
    }
}

// ---------------------------------------------------------------------------
extern "C" void kernel_launch(void* const* d_in, const int* in_sizes, int n_in,
                              void* d_out, int out_size) {
    static const int dims[NF] = {32, 64, 96, 128, 192, 256, 384, 512};
    Ptrs p;
    int wseen[NF] = {0};

    for (int i = 0; i < n_in; i++) {
        const float* ptr = (const float*)d_in[i];
        int s = in_sizes[i];
        if (s == HID) { p.q = ptr; continue; }
        bool matched = false;
        for (int f = 0; f < NF; f++)
            if (s == BATCHN * dims[f]) { p.feat[f] = ptr; matched = true; break; }
        if (matched) continue;
        for (int f = 0; f < NF; f++)
            if (s == HID * dims[f]) {
                if (!wseen[f]) { p.Wk[f] = ptr; wseen[f] = 1; }
                else           { p.Wv[f] = ptr; }
                break;
            }
    }

    cudaFuncSetAttribute(main_kernel, cudaFuncAttributeMaxDynamicSharedMemorySize, SMEM_TOT);

    prep_kernel<<<(HID * KTOT + 255) / 256, 256>>>(p);
    main_kernel<<<BATCHN / MBLK, NTHR, SMEM_TOT>>>(p, (float*)d_out);
}

// round 10
// speedup vs baseline: 1.6265x; 1.4330x over previous
#include <cuda_runtime.h>
#include <cuda_fp16.h>
#include <cstdint>

// ---------------------------------------------------------------------------
// FeatureAttentionPerFeature — mma.sync fp16 2-term split (A single fp16,
// B hi/lo fp16), structure identical to the 182us R7 kernel.
//   scores[b,f] = feat_f[b] . (Wk_f^T q)/sqrt(128)
//   w = softmax_f(scores)
//   combined = (w-scaled concat feats) @ Wv_all^T
// Output: [ combined (B*128) | attn_weights (B*8) ]
// ---------------------------------------------------------------------------

#define NF     8
#define HID    128
#define KTOT   1664
#define BATCHN 32768
#define MBLK   128
#define KCH    64
#define NCH    (KTOT/KCH)    // 26
#define NTHR   256
#define RSTRIDE 144          // smem row stride BYTES, conflict-free

__device__ constexpr int DIMS_C[NF]   = {32, 64, 96, 128, 192, 256, 384, 512};
__device__ constexpr int OFFS_C[NF+1] = {0, 32, 96, 192, 320, 512, 768, 1152, 1664};
__constant__ int gDIMS[NF]   = {32, 64, 96, 128, 192, 256, 384, 512};
__constant__ int gOFFS[NF+1] = {0, 32, 96, 192, 320, 512, 768, 1152, 1664};

// device scratch
__device__ float g_c[KTOT];
__device__ __half g_Bh[HID * KTOT];   // Wv hi (fp16), [n][k] k-major
__device__ __half g_Bl[HID * KTOT];   // Wv lo residual (fp16)

struct Ptrs {
    const float* feat[NF];
    const float* Wk[NF];
    const float* Wv[NF];
    const float* q;
};

// ---------------- helpers ----------------
__device__ __forceinline__ uint32_t smem_u32(const void* p) {
    uint32_t a;
    asm("{ .reg .u64 t; cvta.to.shared.u64 t, %1; cvt.u32.u64 %0, t; }" : "=r"(a) : "l"(p));
    return a;
}
__device__ __forceinline__ void ldsm_x4(uint32_t* r, uint32_t a) {
    asm volatile("ldmatrix.sync.aligned.m8n8.x4.shared.b16 {%0,%1,%2,%3}, [%4];"
                 : "=r"(r[0]), "=r"(r[1]), "=r"(r[2]), "=r"(r[3]) : "r"(a));
}
__device__ __forceinline__ void mma_fp16(float* c, const uint32_t* a, const uint32_t* b) {
    asm volatile(
        "mma.sync.aligned.m16n8k16.row.col.f32.f16.f16.f32 "
        "{%0,%1,%2,%3}, {%4,%5,%6,%7}, {%8,%9}, {%0,%1,%2,%3};"
        : "+f"(c[0]), "+f"(c[1]), "+f"(c[2]), "+f"(c[3])
        : "r"(a[0]), "r"(a[1]), "r"(a[2]), "r"(a[3]), "r"(b[0]), "r"(b[1]));
}
__device__ __forceinline__ int ffind(int k) {
    int f = 7;
    if (k < 1152) f = 6;
    if (k < 768)  f = 5;
    if (k < 512)  f = 4;
    if (k < 320)  f = 3;
    if (k < 192)  f = 2;
    if (k < 96)   f = 1;
    if (k < 32)   f = 0;
    return f;
}

// ---------------- SMEM layout (dynamic, bytes) ----------------
#define OFF_CS  0                        // 1664*4 = 6656
#define OFF_WS  6656                     // 128*8*4 = 4096
#define OFF_AH  10752                    // 128*144 = 18432 (fp16 A tile)
#define OFF_BH  (OFF_AH + 18432)
#define OFF_BL  (OFF_BH + 18432)
#define SMEM_TOT (OFF_BL + 18432)        // 66048

// ---------------------------------------------------------------------------
// prep: c vector (warp per k) + fp16 hi/lo pack of Wv into [n][k]
// ---------------------------------------------------------------------------
__global__ void prep_kernel(Ptrs p) {
    int tid = blockIdx.x * blockDim.x + threadIdx.x;

    if (tid < KTOT * 32) {
        int k = tid >> 5, ln = tid & 31;
        int f = ffind(k);
        int j = k - gOFFS[f];
        int d = gDIMS[f];
        const float* W = p.Wk[f];
        float s = 0.f;
        #pragma unroll
        for (int h = ln; h < HID; h += 32) s += W[h * d + j] * p.q[h];
        #pragma unroll
        for (int o = 16; o; o >>= 1) s += __shfl_xor_sync(0xffffffffu, s, o);
        if (ln == 0) g_c[k] = s * 0.08838834764831845f;
    }

    if (tid < HID * KTOT) {
        int n = tid / KTOT;
        int k = tid % KTOT;
        int f = ffind(k);
        int j = k - gOFFS[f];
        float val = p.Wv[f][n * gDIMS[f] + j];
        __half hi = __float2half_rn(val);
        __half lo = __float2half_rn(val - __half2float(hi));
        g_Bh[tid] = hi;
        g_Bl[tid] = lo;
    }
}

// ---------------------------------------------------------------------------
// main kernel: grid 256 x 256 threads, 2 CTAs/SM
// ---------------------------------------------------------------------------
__global__ void __launch_bounds__(NTHR, 2)
main_kernel(Ptrs p, float* __restrict__ out) {
    extern __shared__ char smem[];
    const uint32_t sb = smem_u32(smem);
    const int t    = threadIdx.x;
    const int lane = t & 31;
    const int wid  = t >> 5;
    const int wm   = wid >> 2;          // 0..1  (64 rows each)
    const int wn   = wid & 3;           // 0..3  (32 cols each)
    const int row0 = blockIdx.x * MBLK;

    float* cs   = (float*)(smem + OFF_CS);
    float* ws_s = (float*)(smem + OFF_WS);

    for (int i = t; i < KTOT; i += NTHR) cs[i] = g_c[i];
    __syncthreads();

    // ---- phase 1: warp-per-row coalesced scores + softmax ----
    {
        #pragma unroll 1
        for (int rr = 0; rr < 16; rr++) {
            const int lrow = wid * 16 + rr;
            const int row  = row0 + lrow;
            float sc[NF];
            #pragma unroll
            for (int f = 0; f < NF; f++) {
                const int d = DIMS_C[f];
                float s = 0.f;
                #pragma unroll
                for (int j0 = 0; j0 < d; j0 += 128) {
                    int j = j0 + lane * 4;
                    if (j < d) {
                        float4 a = *(const float4*)(p.feat[f] + (size_t)row * d + j);
                        float4 b = *(const float4*)(cs + OFFS_C[f] + j);
                        s += a.x * b.x + a.y * b.y + a.z * b.z + a.w * b.w;
                    }
                }
                #pragma unroll
                for (int o = 16; o; o >>= 1) s += __shfl_xor_sync(0xffffffffu, s, o);
                sc[f] = s;
            }
            float m = sc[0];
            #pragma unroll
            for (int f = 1; f < NF; f++) m = fmaxf(m, sc[f]);
            float sum = 0.f;
            #pragma unroll
            for (int f = 0; f < NF; f++) { sc[f] = expf(sc[f] - m); sum += sc[f]; }
            const float inv = 1.f / sum;
            if (lane == 0) {
                float4 w0 = make_float4(sc[0] * inv, sc[1] * inv, sc[2] * inv, sc[3] * inv);
                float4 w1 = make_float4(sc[4] * inv, sc[5] * inv, sc[6] * inv, sc[7] * inv);
                *(float4*)(ws_s + lrow * NF)     = w0;
                *(float4*)(ws_s + lrow * NF + 4) = w1;
                float* ao = out + (size_t)BATCHN * HID + (size_t)row * NF;
                *(float4*)(ao)     = w0;
                *(float4*)(ao + 4) = w1;
            }
        }
    }

    // ---- mainloop ----
    float acc[4][4][4];
    #pragma unroll
    for (int mf = 0; mf < 4; mf++)
        #pragma unroll
        for (int nf = 0; nf < 4; nf++)
            #pragma unroll
            for (int r = 0; r < 4; r++) acc[mf][nf][r] = 0.f;

    // per-lane ldmatrix base offsets (bytes)
    const uint32_t aoff = (uint32_t)((wm * 64 + (lane & 15)) * RSTRIDE + ((lane >> 4) * 8) * 2);
    const uint32_t boff = (uint32_t)((wn * 32 + ((lane >> 4) * 8) + (lane & 7)) * RSTRIDE +
                                     (((lane >> 3) & 1) * 8) * 2);
    const uint32_t sAh = sb + OFF_AH;
    const uint32_t sBh = sb + OFF_BH, sBl = sb + OFF_BL;

    for (int ch = 0; ch < NCH; ch++) {
        const int k0 = ch * KCH;
        __syncthreads();   // previous chunk's ldmatrix done; ws ready (iter 0)

        // --- A convert: 128 rows x 64 k, weighted fp16, single tile ---
        #pragma unroll
        for (int it = 0; it < 4; it++) {
            int g   = it * 256 + t;        // 0..1023
            int row = g >> 3;
            int kq  = g & 7;
            int kg  = k0 + kq * 8;
            int f   = ffind(kg);
            int j   = kg - gOFFS[f];
            const float* src = p.feat[f] + (size_t)(row0 + row) * gDIMS[f] + j;
            float4 v0 = *(const float4*)src;
            float4 v1 = *(const float4*)(src + 4);
            float w = ws_s[row * NF + f];
            float x[8] = {v0.x * w, v0.y * w, v0.z * w, v0.w * w,
                          v1.x * w, v1.y * w, v1.z * w, v1.w * w};
            uint32_t h[4];
            #pragma unroll
            for (int q = 0; q < 4; q++) {
                __half b0 = __float2half_rn(x[2 * q]);
                __half b1 = __float2half_rn(x[2 * q + 1]);
                h[q] = (uint32_t)__half_as_ushort(b0) | ((uint32_t)__half_as_ushort(b1) << 16);
            }
            uint32_t off = (uint32_t)(row * RSTRIDE + kq * 16);
            *(uint4*)(smem + OFF_AH + off) = make_uint4(h[0], h[1], h[2], h[3]);
        }
        // --- B tiles: copy from packed global (L2-resident) ---
        #pragma unroll
        for (int it = 0; it < 4; it++) {
            int g  = it * 256 + t;         // 0..1023
            int n  = g >> 3;
            int kq = g & 7;
            size_t goff = (size_t)n * KTOT + k0 + kq * 8;
            uint32_t off = (uint32_t)(n * RSTRIDE + kq * 16);
            *(uint4*)(smem + OFF_BH + off) = *(const uint4*)&g_Bh[goff];
            *(uint4*)(smem + OFF_BL + off) = *(const uint4*)&g_Bl[goff];
        }
        __syncthreads();

        // --- tensor-core phase: 4 k16 steps, 2 terms each ---
        #pragma unroll
        for (int ks = 0; ks < 4; ks++) {
            const uint32_t koff = ks * 32;   // 16 fp16 = 32 bytes
            uint32_t a[4][4];
            #pragma unroll
            for (int mf = 0; mf < 4; mf++)
                ldsm_x4(a[mf], sAh + aoff + mf * (16 * RSTRIDE) + koff);

            uint32_t bh[4][2], bl[4][2];
            #pragma unroll
            for (int bq = 0; bq < 2; bq++) {
                uint32_t r[4];
                // B stored [n][k] k-contiguous -> NON-trans ldmatrix gives the
                // m16n8k16 row.col B fragment
                ldsm_x4(r, sBh + boff + bq * (16 * RSTRIDE) + koff);
                bh[bq * 2][0] = r[0]; bh[bq * 2][1] = r[1];
                bh[bq * 2 + 1][0] = r[2]; bh[bq * 2 + 1][1] = r[3];
                ldsm_x4(r, sBl + boff + bq * (16 * RSTRIDE) + koff);
                bl[bq * 2][0] = r[0]; bl[bq * 2][1] = r[1];
                bl[bq * 2 + 1][0] = r[2]; bl[bq * 2 + 1][1] = r[3];
            }
            #pragma unroll
            for (int mf = 0; mf < 4; mf++)
                #pragma unroll
                for (int nf = 0; nf < 4; nf++) mma_fp16(acc[mf][nf], a[mf], bh[nf]);
            #pragma unroll
            for (int mf = 0; mf < 4; mf++)
                #pragma unroll
                for (int nf = 0; nf < 4; nf++) mma_fp16(acc[mf][nf], a[mf], bl[nf]);
        }
    }

    // ---- epilogue: write combined ----
    #pragma unroll
    for (int mf = 0; mf < 4; mf++) {
        #pragma unroll
        for (int nf = 0; nf < 4; nf++) {
            int r0 = row0 + wm * 64 + mf * 16 + (lane >> 2);
            int c  = wn * 32 + nf * 8 + (lane & 3) * 2;
            *(float2*)(out + (size_t)r0 * HID + c) =
                make_float2(acc[mf][nf][0], acc[mf][nf][1]);
            *(float2*)(out + (size_t)(r0 + 8) * HID + c) =
                make_float2(acc[mf][nf][2], acc[mf][nf][3]);
        }
    }
}

// ---------------------------------------------------------------------------
extern "C" void kernel_launch(void* const* d_in, const int* in_sizes, int n_in,
                              void* d_out, int out_size) {
    static const int dims[NF] = {32, 64, 96, 128, 192, 256, 384, 512};
    Ptrs p;
    int wseen[NF] = {0};

    for (int i = 0; i < n_in; i++) {
        const float* ptr = (const float*)d_in[i];
        int s = in_sizes[i];
        if (s == HID) { p.q = ptr; continue; }
        bool matched = false;
        for (int f = 0; f < NF; f++)
            if (s == BATCHN * dims[f]) { p.feat[f] = ptr; matched = true; break; }
        if (matched) continue;
        for (int f = 0; f < NF; f++)
            if (s == HID * dims[f]) {
                if (!wseen[f]) { p.Wk[f] = ptr; wseen[f] = 1; }
                else           { p.Wv[f] = ptr; }
                break;
            }
    }

    cudaFuncSetAttribute(main_kernel, cudaFuncAttributeMaxDynamicSharedMemorySize, SMEM_TOT);

    prep_kernel<<<(HID * KTOT + 255) / 256, 256>>>(p);
    main_kernel<<<BATCHN / MBLK, NTHR, SMEM_TOT>>>(p, (float*)d_out);
}

// round 11
// speedup vs baseline: 1.9244x; 1.1831x over previous
#include <cuda_runtime.h>
#include <cuda_fp16.h>
#include <cstdint>

// ---------------------------------------------------------------------------
// FeatureAttentionPerFeature — mma.sync pure fp16 (single term, A and B fp16)
//   scores[b,f] = feat_f[b] . (Wk_f^T q)/sqrt(128)
//   w = softmax_f(scores)
//   combined = (w-scaled concat feats) @ Wv_all^T
// Output: [ combined (B*128) | attn_weights (B*8) ]
// R11: dropped B hi/lo split (error budget: A-fp16 2.1e-4 ⊕ B-fp16 ~2e-4 ≈ 3e-4)
// ---------------------------------------------------------------------------

#define NF     8
#define HID    128
#define KTOT   1664
#define BATCHN 32768
#define MBLK   128
#define KCH    64
#define NCH    (KTOT/KCH)    // 26
#define NTHR   256
#define RSTRIDE 144          // smem row stride BYTES, conflict-free

__device__ constexpr int DIMS_C[NF]   = {32, 64, 96, 128, 192, 256, 384, 512};
__device__ constexpr int OFFS_C[NF+1] = {0, 32, 96, 192, 320, 512, 768, 1152, 1664};
__constant__ int gDIMS[NF]   = {32, 64, 96, 128, 192, 256, 384, 512};
__constant__ int gOFFS[NF+1] = {0, 32, 96, 192, 320, 512, 768, 1152, 1664};

// device scratch
__device__ float g_c[KTOT];
__device__ __half g_Bh[HID * KTOT];   // Wv (fp16), [n][k] k-major

struct Ptrs {
    const float* feat[NF];
    const float* Wk[NF];
    const float* Wv[NF];
    const float* q;
};

// ---------------- helpers ----------------
__device__ __forceinline__ uint32_t smem_u32(const void* p) {
    uint32_t a;
    asm("{ .reg .u64 t; cvta.to.shared.u64 t, %1; cvt.u32.u64 %0, t; }" : "=r"(a) : "l"(p));
    return a;
}
__device__ __forceinline__ void ldsm_x4(uint32_t* r, uint32_t a) {
    asm volatile("ldmatrix.sync.aligned.m8n8.x4.shared.b16 {%0,%1,%2,%3}, [%4];"
                 : "=r"(r[0]), "=r"(r[1]), "=r"(r[2]), "=r"(r[3]) : "r"(a));
}
__device__ __forceinline__ void mma_fp16(float* c, const uint32_t* a, const uint32_t* b) {
    asm volatile(
        "mma.sync.aligned.m16n8k16.row.col.f32.f16.f16.f32 "
        "{%0,%1,%2,%3}, {%4,%5,%6,%7}, {%8,%9}, {%0,%1,%2,%3};"
        : "+f"(c[0]), "+f"(c[1]), "+f"(c[2]), "+f"(c[3])
        : "r"(a[0]), "r"(a[1]), "r"(a[2]), "r"(a[3]), "r"(b[0]), "r"(b[1]));
}
__device__ __forceinline__ int ffind(int k) {
    int f = 7;
    if (k < 1152) f = 6;
    if (k < 768)  f = 5;
    if (k < 512)  f = 4;
    if (k < 320)  f = 3;
    if (k < 192)  f = 2;
    if (k < 96)   f = 1;
    if (k < 32)   f = 0;
    return f;
}

// ---------------- SMEM layout (dynamic, bytes) ----------------
#define OFF_CS  0                        // 1664*4 = 6656
#define OFF_WS  6656                     // 128*8*4 = 4096
#define OFF_AH  10752                    // 128*144 = 18432 (fp16 A tile)
#define OFF_BH  (OFF_AH + 18432)
#define SMEM_TOT (OFF_BH + 18432)        // 47616

// ---------------------------------------------------------------------------
// prep: c vector (warp per k) + fp16 pack of Wv into [n][k]
// ---------------------------------------------------------------------------
__global__ void prep_kernel(Ptrs p) {
    int tid = blockIdx.x * blockDim.x + threadIdx.x;

    if (tid < KTOT * 32) {
        int k = tid >> 5, ln = tid & 31;
        int f = ffind(k);
        int j = k - gOFFS[f];
        int d = gDIMS[f];
        const float* W = p.Wk[f];
        float s = 0.f;
        #pragma unroll
        for (int h = ln; h < HID; h += 32) s += W[h * d + j] * p.q[h];
        #pragma unroll
        for (int o = 16; o; o >>= 1) s += __shfl_xor_sync(0xffffffffu, s, o);
        if (ln == 0) g_c[k] = s * 0.08838834764831845f;
    }

    if (tid < HID * KTOT) {
        int n = tid / KTOT;
        int k = tid % KTOT;
        int f = ffind(k);
        int j = k - gOFFS[f];
        g_Bh[tid] = __float2half_rn(p.Wv[f][n * gDIMS[f] + j]);
    }
}

// ---------------------------------------------------------------------------
// main kernel: grid 256 x 256 threads, 2 CTAs/SM
// ---------------------------------------------------------------------------
__global__ void __launch_bounds__(NTHR, 2)
main_kernel(Ptrs p, float* __restrict__ out) {
    extern __shared__ char smem[];
    const uint32_t sb = smem_u32(smem);
    const int t    = threadIdx.x;
    const int lane = t & 31;
    const int wid  = t >> 5;
    const int wm   = wid >> 2;          // 0..1  (64 rows each)
    const int wn   = wid & 3;           // 0..3  (32 cols each)
    const int row0 = blockIdx.x * MBLK;

    float* cs   = (float*)(smem + OFF_CS);
    float* ws_s = (float*)(smem + OFF_WS);

    for (int i = t; i < KTOT; i += NTHR) cs[i] = g_c[i];
    __syncthreads();

    // ---- phase 1: warp-per-row coalesced scores + softmax ----
    {
        #pragma unroll 1
        for (int rr = 0; rr < 16; rr++) {
            const int lrow = wid * 16 + rr;
            const int row  = row0 + lrow;
            float sc[NF];
            #pragma unroll
            for (int f = 0; f < NF; f++) {
                const int d = DIMS_C[f];
                float s = 0.f;
                #pragma unroll
                for (int j0 = 0; j0 < d; j0 += 128) {
                    int j = j0 + lane * 4;
                    if (j < d) {
                        float4 a = *(const float4*)(p.feat[f] + (size_t)row * d + j);
                        float4 b = *(const float4*)(cs + OFFS_C[f] + j);
                        s += a.x * b.x + a.y * b.y + a.z * b.z + a.w * b.w;
                    }
                }
                #pragma unroll
                for (int o = 16; o; o >>= 1) s += __shfl_xor_sync(0xffffffffu, s, o);
                sc[f] = s;
            }
            float m = sc[0];
            #pragma unroll
            for (int f = 1; f < NF; f++) m = fmaxf(m, sc[f]);
            float sum = 0.f;
            #pragma unroll
            for (int f = 0; f < NF; f++) { sc[f] = expf(sc[f] - m); sum += sc[f]; }
            const float inv = 1.f / sum;
            if (lane == 0) {
                float4 w0 = make_float4(sc[0] * inv, sc[1] * inv, sc[2] * inv, sc[3] * inv);
                float4 w1 = make_float4(sc[4] * inv, sc[5] * inv, sc[6] * inv, sc[7] * inv);
                *(float4*)(ws_s + lrow * NF)     = w0;
                *(float4*)(ws_s + lrow * NF + 4) = w1;
                float* ao = out + (size_t)BATCHN * HID + (size_t)row * NF;
                *(float4*)(ao)     = w0;
                *(float4*)(ao + 4) = w1;
            }
        }
    }

    // ---- mainloop ----
    float acc[4][4][4];
    #pragma unroll
    for (int mf = 0; mf < 4; mf++)
        #pragma unroll
        for (int nf = 0; nf < 4; nf++)
            #pragma unroll
            for (int r = 0; r < 4; r++) acc[mf][nf][r] = 0.f;

    // per-lane ldmatrix base offsets (bytes)
    const uint32_t aoff = (uint32_t)((wm * 64 + (lane & 15)) * RSTRIDE + ((lane >> 4) * 8) * 2);
    const uint32_t boff = (uint32_t)((wn * 32 + ((lane >> 4) * 8) + (lane & 7)) * RSTRIDE +
                                     (((lane >> 3) & 1) * 8) * 2);
    const uint32_t sAh = sb + OFF_AH;
    const uint32_t sBh = sb + OFF_BH;

    for (int ch = 0; ch < NCH; ch++) {
        const int k0 = ch * KCH;
        __syncthreads();   // previous chunk's ldmatrix done; ws ready (iter 0)

        // --- A convert: 128 rows x 64 k, weighted fp16, single tile ---
        #pragma unroll
        for (int it = 0; it < 4; it++) {
            int g   = it * 256 + t;        // 0..1023
            int row = g >> 3;
            int kq  = g & 7;
            int kg  = k0 + kq * 8;
            int f   = ffind(kg);
            int j   = kg - gOFFS[f];
            const float* src = p.feat[f] + (size_t)(row0 + row) * gDIMS[f] + j;
            float4 v0 = *(const float4*)src;
            float4 v1 = *(const float4*)(src + 4);
            float w = ws_s[row * NF + f];
            float x[8] = {v0.x * w, v0.y * w, v0.z * w, v0.w * w,
                          v1.x * w, v1.y * w, v1.z * w, v1.w * w};
            uint32_t h[4];
            #pragma unroll
            for (int q = 0; q < 4; q++) {
                __half b0 = __float2half_rn(x[2 * q]);
                __half b1 = __float2half_rn(x[2 * q + 1]);
                h[q] = (uint32_t)__half_as_ushort(b0) | ((uint32_t)__half_as_ushort(b1) << 16);
            }
            uint32_t off = (uint32_t)(row * RSTRIDE + kq * 16);
            *(uint4*)(smem + OFF_AH + off) = make_uint4(h[0], h[1], h[2], h[3]);
        }
        // --- B tile: copy from packed global (L2-resident) ---
        #pragma unroll
        for (int it = 0; it < 4; it++) {
            int g  = it * 256 + t;         // 0..1023
            int n  = g >> 3;
            int kq = g & 7;
            size_t goff = (size_t)n * KTOT + k0 + kq * 8;
            uint32_t off = (uint32_t)(n * RSTRIDE + kq * 16);
            *(uint4*)(smem + OFF_BH + off) = *(const uint4*)&g_Bh[goff];
        }
        __syncthreads();

        // --- tensor-core phase: 4 k16 steps, single term ---
        #pragma unroll
        for (int ks = 0; ks < 4; ks++) {
            const uint32_t koff = ks * 32;   // 16 fp16 = 32 bytes
            uint32_t a[4][4];
            #pragma unroll
            for (int mf = 0; mf < 4; mf++)
                ldsm_x4(a[mf], sAh + aoff + mf * (16 * RSTRIDE) + koff);

            uint32_t bh[4][2];
            #pragma unroll
            for (int bq = 0; bq < 2; bq++) {
                uint32_t r[4];
                // B stored [n][k] k-contiguous -> NON-trans ldmatrix gives the
                // m16n8k16 row.col B fragment
                ldsm_x4(r, sBh + boff + bq * (16 * RSTRIDE) + koff);
                bh[bq * 2][0] = r[0]; bh[bq * 2][1] = r[1];
                bh[bq * 2 + 1][0] = r[2]; bh[bq * 2 + 1][1] = r[3];
            }
            #pragma unroll
            for (int mf = 0; mf < 4; mf++)
                #pragma unroll
                for (int nf = 0; nf < 4; nf++) mma_fp16(acc[mf][nf], a[mf], bh[nf]);
        }
    }

    // ---- epilogue: write combined ----
    #pragma unroll
    for (int mf = 0; mf < 4; mf++) {
        #pragma unroll
        for (int nf = 0; nf < 4; nf++) {
            int r0 = row0 + wm * 64 + mf * 16 + (lane >> 2);
            int c  = wn * 32 + nf * 8 + (lane & 3) * 2;
            *(float2*)(out + (size_t)r0 * HID + c) =
                make_float2(acc[mf][nf][0], acc[mf][nf][1]);
            *(float2*)(out + (size_t)(r0 + 8) * HID + c) =
                make_float2(acc[mf][nf][2], acc[mf][nf][3]);
        }
    }
}

// ---------------------------------------------------------------------------
extern "C" void kernel_launch(void* const* d_in, const int* in_sizes, int n_in,
                              void* d_out, int out_size) {
    static const int dims[NF] = {32, 64, 96, 128, 192, 256, 384, 512};
    Ptrs p;
    int wseen[NF] = {0};

    for (int i = 0; i < n_in; i++) {
        const float* ptr = (const float*)d_in[i];
        int s = in_sizes[i];
        if (s == HID) { p.q = ptr; continue; }
        bool matched = false;
        for (int f = 0; f < NF; f++)
            if (s == BATCHN * dims[f]) { p.feat[f] = ptr; matched = true; break; }
        if (matched) continue;
        for (int f = 0; f < NF; f++)
            if (s == HID * dims[f]) {
                if (!wseen[f]) { p.Wk[f] = ptr; wseen[f] = 1; }
                else           { p.Wv[f] = ptr; }
                break;
            }
    }

    cudaFuncSetAttribute(main_kernel, cudaFuncAttributeMaxDynamicSharedMemorySize, SMEM_TOT);

    prep_kernel<<<(HID * KTOT + 255) / 256, 256>>>(p);
    main_kernel<<<BATCHN / MBLK, NTHR, SMEM_TOT>>>(p, (float*)d_out);
}

// round 12
// speedup vs baseline: 1.9442x; 1.0103x over previous
#include <cuda_runtime.h>
#include <cuda_fp16.h>
#include <cstdint>

// ---------------------------------------------------------------------------
// FeatureAttentionPerFeature — mma.sync pure fp16, R12: MLP-optimized
//   scores[b,f] = feat_f[b] . (Wk_f^T q)/sqrt(128)
//   w = softmax_f(scores)
//   combined = (w-scaled concat feats) @ Wv_all^T
// Output: [ combined (B*128) | attn_weights (B*8) ]
// R12: KCH=128 (half the barriers, deeper load batching), phase-1 deferred
//      shfl reductions (front-batched feature loads).
// ---------------------------------------------------------------------------

#define NF     8
#define HID    128
#define KTOT   1664
#define BATCHN 32768
#define MBLK   128
#define KCH    128
#define NCH    (KTOT/KCH)    // 13
#define NTHR   256
#define RSTRIDE 272          // smem row stride BYTES (256 data + 16 pad)

__device__ constexpr int DIMS_C[NF]   = {32, 64, 96, 128, 192, 256, 384, 512};
__device__ constexpr int OFFS_C[NF+1] = {0, 32, 96, 192, 320, 512, 768, 1152, 1664};
__constant__ int gDIMS[NF]   = {32, 64, 96, 128, 192, 256, 384, 512};
__constant__ int gOFFS[NF+1] = {0, 32, 96, 192, 320, 512, 768, 1152, 1664};

// device scratch
__device__ float g_c[KTOT];
__device__ __half g_Bh[HID * KTOT];   // Wv (fp16), [n][k] k-major

struct Ptrs {
    const float* feat[NF];
    const float* Wk[NF];
    const float* Wv[NF];
    const float* q;
};

// ---------------- helpers ----------------
__device__ __forceinline__ uint32_t smem_u32(const void* p) {
    uint32_t a;
    asm("{ .reg .u64 t; cvta.to.shared.u64 t, %1; cvt.u32.u64 %0, t; }" : "=r"(a) : "l"(p));
    return a;
}
__device__ __forceinline__ void ldsm_x4(uint32_t* r, uint32_t a) {
    asm volatile("ldmatrix.sync.aligned.m8n8.x4.shared.b16 {%0,%1,%2,%3}, [%4];"
                 : "=r"(r[0]), "=r"(r[1]), "=r"(r[2]), "=r"(r[3]) : "r"(a));
}
__device__ __forceinline__ void mma_fp16(float* c, const uint32_t* a, const uint32_t* b) {
    asm volatile(
        "mma.sync.aligned.m16n8k16.row.col.f32.f16.f16.f32 "
        "{%0,%1,%2,%3}, {%4,%5,%6,%7}, {%8,%9}, {%0,%1,%2,%3};"
        : "+f"(c[0]), "+f"(c[1]), "+f"(c[2]), "+f"(c[3])
        : "r"(a[0]), "r"(a[1]), "r"(a[2]), "r"(a[3]), "r"(b[0]), "r"(b[1]));
}
__device__ __forceinline__ int ffind(int k) {
    int f = 7;
    if (k < 1152) f = 6;
    if (k < 768)  f = 5;
    if (k < 512)  f = 4;
    if (k < 320)  f = 3;
    if (k < 192)  f = 2;
    if (k < 96)   f = 1;
    if (k < 32)   f = 0;
    return f;
}

// ---------------- SMEM layout (dynamic, bytes) ----------------
#define OFF_CS  0                        // 1664*4 = 6656
#define OFF_WS  6656                     // 128*8*4 = 4096
#define OFF_AH  10752                    // 128*272 = 34816 (fp16 A tile)
#define OFF_BH  (OFF_AH + 34816)
#define SMEM_TOT (OFF_BH + 34816)        // 80384  (2 CTAs/SM)

// ---------------------------------------------------------------------------
// prep: c vector (warp per k) + fp16 pack of Wv into [n][k]
// ---------------------------------------------------------------------------
__global__ void prep_kernel(Ptrs p) {
    int tid = blockIdx.x * blockDim.x + threadIdx.x;

    if (tid < KTOT * 32) {
        int k = tid >> 5, ln = tid & 31;
        int f = ffind(k);
        int j = k - gOFFS[f];
        int d = gDIMS[f];
        const float* W = p.Wk[f];
        float s = 0.f;
        #pragma unroll
        for (int h = ln; h < HID; h += 32) s += W[h * d + j] * p.q[h];
        #pragma unroll
        for (int o = 16; o; o >>= 1) s += __shfl_xor_sync(0xffffffffu, s, o);
        if (ln == 0) g_c[k] = s * 0.08838834764831845f;
    }

    if (tid < HID * KTOT) {
        int n = tid / KTOT;
        int k = tid % KTOT;
        int f = ffind(k);
        int j = k - gOFFS[f];
        g_Bh[tid] = __float2half_rn(p.Wv[f][n * gDIMS[f] + j]);
    }
}

// ---------------------------------------------------------------------------
// main kernel: grid 256 x 256 threads, 2 CTAs/SM
// ---------------------------------------------------------------------------
__global__ void __launch_bounds__(NTHR, 2)
main_kernel(Ptrs p, float* __restrict__ out) {
    extern __shared__ char smem[];
    const uint32_t sb = smem_u32(smem);
    const int t    = threadIdx.x;
    const int lane = t & 31;
    const int wid  = t >> 5;
    const int wm   = wid >> 2;          // 0..1  (64 rows each)
    const int wn   = wid & 3;           // 0..3  (32 cols each)
    const int row0 = blockIdx.x * MBLK;

    float* cs   = (float*)(smem + OFF_CS);
    float* ws_s = (float*)(smem + OFF_WS);

    for (int i = t; i < KTOT; i += NTHR) cs[i] = g_c[i];
    __syncthreads();

    // ---- phase 1: warp-per-row scores + softmax, deferred reductions ----
    {
        #pragma unroll 1
        for (int rr = 0; rr < 16; rr++) {
            const int lrow = wid * 16 + rr;
            const int row  = row0 + lrow;
            float sc[NF];
            // per-lane partials for ALL features first -> loads front-batch
            #pragma unroll
            for (int f = 0; f < NF; f++) {
                const int d = DIMS_C[f];
                float s = 0.f;
                #pragma unroll
                for (int j0 = 0; j0 < d; j0 += 128) {
                    int j = j0 + lane * 4;
                    if (j < d) {
                        float4 a = *(const float4*)(p.feat[f] + (size_t)row * d + j);
                        float4 b = *(const float4*)(cs + OFFS_C[f] + j);
                        s += a.x * b.x + a.y * b.y + a.z * b.z + a.w * b.w;
                    }
                }
                sc[f] = s;
            }
            // now reduce all 8
            #pragma unroll
            for (int f = 0; f < NF; f++) {
                #pragma unroll
                for (int o = 16; o; o >>= 1)
                    sc[f] += __shfl_xor_sync(0xffffffffu, sc[f], o);
            }
            float m = sc[0];
            #pragma unroll
            for (int f = 1; f < NF; f++) m = fmaxf(m, sc[f]);
            float sum = 0.f;
            #pragma unroll
            for (int f = 0; f < NF; f++) { sc[f] = expf(sc[f] - m); sum += sc[f]; }
            const float inv = 1.f / sum;
            if (lane == 0) {
                float4 w0 = make_float4(sc[0] * inv, sc[1] * inv, sc[2] * inv, sc[3] * inv);
                float4 w1 = make_float4(sc[4] * inv, sc[5] * inv, sc[6] * inv, sc[7] * inv);
                *(float4*)(ws_s + lrow * NF)     = w0;
                *(float4*)(ws_s + lrow * NF + 4) = w1;
                float* ao = out + (size_t)BATCHN * HID + (size_t)row * NF;
                *(float4*)(ao)     = w0;
                *(float4*)(ao + 4) = w1;
            }
        }
    }

    // ---- mainloop ----
    float acc[4][4][4];
    #pragma unroll
    for (int mf = 0; mf < 4; mf++)
        #pragma unroll
        for (int nf = 0; nf < 4; nf++)
            #pragma unroll
            for (int r = 0; r < 4; r++) acc[mf][nf][r] = 0.f;

    // per-lane ldmatrix base offsets (bytes)
    const uint32_t aoff = (uint32_t)((wm * 64 + (lane & 15)) * RSTRIDE + (lane >> 4) * 16);
    const uint32_t boff = (uint32_t)((wn * 32 + ((lane >> 4) * 8) + (lane & 7)) * RSTRIDE +
                                     ((lane >> 3) & 1) * 16);
    const uint32_t sAh = sb + OFF_AH;
    const uint32_t sBh = sb + OFF_BH;

    for (int ch = 0; ch < NCH; ch++) {
        const int k0 = ch * KCH;
        __syncthreads();   // previous chunk's ldmatrix done; ws ready (iter 0)

        // --- A convert: 128 rows x 128 k, weighted fp16 ---
        #pragma unroll
        for (int it = 0; it < 8; it++) {
            int g   = it * 256 + t;        // 0..2047
            int row = g >> 4;
            int kq  = g & 15;              // 16 groups of 8 k
            int kg  = k0 + kq * 8;
            int f   = ffind(kg);
            int j   = kg - gOFFS[f];
            const float* src = p.feat[f] + (size_t)(row0 + row) * gDIMS[f] + j;
            float4 v0 = *(const float4*)src;
            float4 v1 = *(const float4*)(src + 4);
            float w = ws_s[row * NF + f];
            float x[8] = {v0.x * w, v0.y * w, v0.z * w, v0.w * w,
                          v1.x * w, v1.y * w, v1.z * w, v1.w * w};
            uint32_t h[4];
            #pragma unroll
            for (int q = 0; q < 4; q++) {
                __half b0 = __float2half_rn(x[2 * q]);
                __half b1 = __float2half_rn(x[2 * q + 1]);
                h[q] = (uint32_t)__half_as_ushort(b0) | ((uint32_t)__half_as_ushort(b1) << 16);
            }
            uint32_t off = (uint32_t)(row * RSTRIDE + kq * 16);
            *(uint4*)(smem + OFF_AH + off) = make_uint4(h[0], h[1], h[2], h[3]);
        }
        // --- B tile: copy from packed global (L2-resident) ---
        #pragma unroll
        for (int it = 0; it < 8; it++) {
            int g  = it * 256 + t;         // 0..2047
            int n  = g >> 4;
            int kq = g & 15;
            size_t goff = (size_t)n * KTOT + k0 + kq * 8;
            uint32_t off = (uint32_t)(n * RSTRIDE + kq * 16);
            *(uint4*)(smem + OFF_BH + off) = *(const uint4*)&g_Bh[goff];
        }
        __syncthreads();

        // --- tensor-core phase: 8 k16 steps ---
        #pragma unroll
        for (int ks = 0; ks < 8; ks++) {
            const uint32_t koff = ks * 32;   // 16 fp16 = 32 bytes
            uint32_t a[4][4];
            #pragma unroll
            for (int mf = 0; mf < 4; mf++)
                ldsm_x4(a[mf], sAh + aoff + mf * (16 * RSTRIDE) + koff);

            uint32_t bh[4][2];
            #pragma unroll
            for (int bq = 0; bq < 2; bq++) {
                uint32_t r[4];
                ldsm_x4(r, sBh + boff + bq * (16 * RSTRIDE) + koff);
                bh[bq * 2][0] = r[0]; bh[bq * 2][1] = r[1];
                bh[bq * 2 + 1][0] = r[2]; bh[bq * 2 + 1][1] = r[3];
            }
            #pragma unroll
            for (int mf = 0; mf < 4; mf++)
                #pragma unroll
                for (int nf = 0; nf < 4; nf++) mma_fp16(acc[mf][nf], a[mf], bh[nf]);
        }
    }

    // ---- epilogue: write combined ----
    #pragma unroll
    for (int mf = 0; mf < 4; mf++) {
        #pragma unroll
        for (int nf = 0; nf < 4; nf++) {
            int r0 = row0 + wm * 64 + mf * 16 + (lane >> 2);
            int c  = wn * 32 + nf * 8 + (lane & 3) * 2;
            *(float2*)(out + (size_t)r0 * HID + c) =
                make_float2(acc[mf][nf][0], acc[mf][nf][1]);
            *(float2*)(out + (size_t)(r0 + 8) * HID + c) =
                make_float2(acc[mf][nf][2], acc[mf][nf][3]);
        }
    }
}

// ---------------------------------------------------------------------------
extern "C" void kernel_launch(void* const* d_in, const int* in_sizes, int n_in,
                              void* d_out, int out_size) {
    static const int dims[NF] = {32, 64, 96, 128, 192, 256, 384, 512};
    Ptrs p;
    int wseen[NF] = {0};

    for (int i = 0; i < n_in; i++) {
        const float* ptr = (const float*)d_in[i];
        int s = in_sizes[i];
        if (s == HID) { p.q = ptr; continue; }
        bool matched = false;
        for (int f = 0; f < NF; f++)
            if (s == BATCHN * dims[f]) { p.feat[f] = ptr; matched = true; break; }
        if (matched) continue;
        for (int f = 0; f < NF; f++)
            if (s == HID * dims[f]) {
                if (!wseen[f]) { p.Wk[f] = ptr; wseen[f] = 1; }
                else           { p.Wv[f] = ptr; }
                break;
            }
    }

    cudaFuncSetAttribute(main_kernel, cudaFuncAttributeMaxDynamicSharedMemorySize, SMEM_TOT);

    prep_kernel<<<(HID * KTOT + 255) / 256, 256>>>(p);
    main_kernel<<<BATCHN / MBLK, NTHR, SMEM_TOT>>>(p, (float*)d_out);
}